// round 9
// baseline (speedup 1.0000x reference)
#include <cuda_runtime.h>
#include <cuda_bf16.h>
#include <cstdint>

// ---------------- problem constants ----------------
#define T_STEPS 200
#define BATCH   256
#define RES     2048
#define OUTD    2
#define BETA    0.9f
#define THRESH  1.0f
#define SPK_ELEMS ((size_t)T_STEPS * BATCH * RES)
#define NSPLIT 3

// GEMM tiling: CTA 64(M) x 64(N), k-chunk 64, 256 threads (8 warps, 2x4),
// warp tile 32(M) x 16(N), mma.sync m16n8k16 bf16.
// Persistent kernel, V in registers. NO global barrier: per-tile flag sync.
// A-chunk c of m-group g is produced by exactly one CTA (n-tile c, m-group g);
// consumers poll g_flags[g][c] (completed-epilogue count) before cp.async.
// Split rings: A 4 x 8KB, B 6 x 24KB (B static -> prefetched across steps).
#define BM 64
#define BN 64
#define BK 64
#define KCHUNKS (RES / BK)              // 32
#define ROW_BYTES 4096                  // 2048 bf16 per row
#define A_STAGE 8192
#define B_STAGE 24576
#define NB_STAGE 6
#define SMEM_DYN (4 * A_STAGE + NB_STAGE * B_STAGE)   // 180224

// ---------------- device state ----------------
__device__ __nv_bfloat16 g_S[2 * BATCH * RES];                    // spike double buffer
__device__ __nv_bfloat16 g_W3[(size_t)NSPLIT * RES * RES];        // split W, [s][n][k]
__device__ unsigned g_flags[4 * KCHUNKS];                         // [m_group][chunk]

// ---------------- helpers ----------------
__device__ __forceinline__ uint32_t smem_u32(const void* p) {
    uint32_t a;
    asm("{ .reg .u64 t; cvta.to.shared.u64 t, %1; cvt.u32.u64 %0, t; }" : "=r"(a) : "l"(p));
    return a;
}

__device__ __forceinline__ void ldsm4(uint32_t* r, uint32_t addr) {
    asm volatile("ldmatrix.sync.aligned.m8n8.x4.shared.b16 {%0,%1,%2,%3}, [%4];"
                 : "=r"(r[0]), "=r"(r[1]), "=r"(r[2]), "=r"(r[3]) : "r"(addr));
}

__device__ __forceinline__ void mma16816(float* c, const uint32_t* a, uint32_t b0, uint32_t b1) {
    asm volatile("mma.sync.aligned.m16n8k16.row.col.f32.bf16.bf16.f32 "
                 "{%0,%1,%2,%3}, {%4,%5,%6,%7}, {%8,%9}, {%0,%1,%2,%3};"
                 : "+f"(c[0]), "+f"(c[1]), "+f"(c[2]), "+f"(c[3])
                 : "r"(a[0]), "r"(a[1]), "r"(a[2]), "r"(a[3]), "r"(b0), "r"(b1));
}

#define CP_COMMIT() asm volatile("cp.async.commit_group;" ::: "memory")
#define CP_WAIT2()  asm volatile("cp.async.wait_group 2;" ::: "memory")

// spin until *f >= want (acquire; orders subsequent cp.async reads)
__device__ __forceinline__ void wait_flag(const unsigned* f, unsigned want) {
    unsigned v;
    #pragma unroll 1
    do {
        asm volatile("ld.acquire.gpu.global.u32 %0, [%1];" : "=r"(v) : "l"(f));
    } while (v < want);
}

// 64x64 bf16 tile (8KB): rows of 128B = 8 x 16B chunks, chunk ^= row%8 swizzle.
// 256 threads, 2 x 16B cp.async each.
__device__ __forceinline__ void load_tile256(uint32_t sbase, const char* g) {
    const int tid = threadIdx.x;
    #pragma unroll
    for (int i = 0; i < 2; i++) {
        int c = tid + i * 256;
        int row = c >> 3, ch = c & 7;
        uint32_t dst = sbase + row * 128 + ((ch ^ (row & 7)) << 4);
        const char* src = g + (size_t)row * ROW_BYTES + ch * 16;
        asm volatile("cp.async.cg.shared.global [%0], [%1], 16;" :: "r"(dst), "l"(src));
    }
}

// load B for one chunk (3 split tiles) into one B stage
__device__ __forceinline__ void load_B(uint32_t stage, const char* gB, int chunk, size_t sstr) {
    #pragma unroll
    for (int s = 0; s < NSPLIT; s++)
        load_tile256(stage + s * A_STAGE, gB + (size_t)s * sstr + (size_t)chunk * 128);
}

// ---------------------------------------------------------------------------
__global__ void init_kernel() {
    const int i = threadIdx.x;
    if (i < 4 * KCHUNKS) g_flags[i] = 0u;
}

// split+transpose W: g_W3[s][n][k] = bf16 split s of W[k][n]
__global__ void split_kernel(const float* __restrict__ W) {
    __shared__ float sh[32][33];
    const int k0 = blockIdx.x * 32;
    const int n0 = blockIdx.y * 32;
    const int tx = threadIdx.x;
    const int ty = threadIdx.y;
    #pragma unroll
    for (int i = ty; i < 32; i += 8)
        sh[i][tx] = W[(size_t)(k0 + i) * RES + n0 + tx];
    __syncthreads();
    #pragma unroll
    for (int i = ty; i < 32; i += 8) {
        float w = sh[tx][i];  // = W[k0+tx][n0+i]
        __nv_bfloat16 b0 = __float2bfloat16(w);
        float r1 = w - __bfloat162float(b0);
        __nv_bfloat16 b1 = __float2bfloat16(r1);
        float r2 = r1 - __bfloat162float(b1);
        __nv_bfloat16 b2 = __float2bfloat16(r2);
        size_t o = (size_t)(n0 + i) * RES + k0 + tx;
        g_W3[o]                         = b0;
        g_W3[(size_t)RES * RES + o]     = b1;
        g_W3[(size_t)2 * RES * RES + o] = b2;
    }
}

// ---------------------------------------------------------------------------
// persistent reservoir kernel: all 200 timesteps, flag-based cross-CTA sync.
// ---------------------------------------------------------------------------
__global__ void __launch_bounds__(256, 1)
reservoir_kernel(const float* __restrict__ x,
                 const float* __restrict__ Win,
                 float* __restrict__ out)
{
    extern __shared__ __align__(128) char dsm[];

    const int tid  = threadIdx.x;
    const int lane = tid & 31;
    const int warp = tid >> 5;
    const int n0 = blockIdx.x * BN;
    const int m0 = blockIdx.y * BM;
    const unsigned* mflags = g_flags + blockIdx.y * KCHUNKS;
    unsigned* myflag = g_flags + blockIdx.y * KCHUNKS + blockIdx.x;
    const int wm = warp >> 2;        // 0..1 -> m offset *32
    const int wn = warp & 3;         // 0..3 -> n offset *16
    const int grp  = lane >> 3;      // ldmatrix address group
    const int lrow = lane & 7;
    const int lr = lane >> 2;        // mma frag row
    const int lc = lane & 3;         // mma frag col pair

    const uint32_t sbA = smem_u32(dsm);
    const uint32_t sbB = sbA + 4 * A_STAGE;
    const char* gB = (const char*)g_W3 + (size_t)n0 * ROW_BYTES;
    const size_t SSTR = (size_t)RES * RES * 2;   // split stride (bytes)

    // this thread's 4 epilogue n-columns: wn*16 + nt*8 + lc*2 + {0,1}
    float wv[4][3];
    #pragma unroll
    for (int nt = 0; nt < 2; nt++)
        #pragma unroll
        for (int q = 0; q < 2; q++) {
            const int nl = wn * 16 + nt * 8 + lc * 2 + q;
            wv[nt * 2 + q][0] = Win[(n0 + nl) * 3 + 0];
            wv[nt * 2 + q][1] = Win[(n0 + nl) * 3 + 1];
            wv[nt * 2 + q][2] = Win[(n0 + nl) * 3 + 2];
        }

    // ldmatrix per-thread row bases (constant across steps)
    const int rowA0 = wm * 32 + (grp & 1) * 8 + lrow;
    const int rowA1 = rowA0 + 16;
    const int rowB  = wn * 16 + (grp >> 1) * 8 + lrow;
    const uint32_t aOff0 = rowA0 * 128, aOff1 = rowA1 * 128, bOff = rowB * 128;
    const int a7_0 = rowA0 & 7, a7_1 = rowA1 & 7, b7 = rowB & 7;
    const int akh = grp >> 1, bkh = grp & 1;

    // membrane potential in registers: V[mi][r][nt][2]
    float V[2][2][2][2];
    #pragma unroll
    for (int a = 0; a < 2; a++)
        #pragma unroll
        for (int b = 0; b < 2; b++)
            #pragma unroll
            for (int c = 0; c < 2; c++)
                V[a][b][c][0] = V[a][b][c][1] = 0.0f;

    // preload B chunks 0..4 into B slots 0..4 (5 groups)
    #pragma unroll
    for (int p = 0; p < 5; p++) {
        load_B(sbB + p * B_STAGE, gB, p, SSTR);
        CP_COMMIT();
    }

    int bslot = 0;  // continuous B ring cursor (mod 6)

    #pragma unroll 1
    for (int t = 0; t < T_STEPS; t++) {
        float acc[2][2][4];
        #pragma unroll
        for (int a = 0; a < 2; a++)
            #pragma unroll
            for (int b = 0; b < 2; b++)
                #pragma unroll
                for (int c = 0; c < 4; c++) acc[a][b][c] = 0.0f;

        if (t > 0) {
            const char* gA = (const char*)g_S
                + (size_t)((t + 1) & 1) * BATCH * RES * 2 + (size_t)m0 * ROW_BYTES;

            #pragma unroll 1
            for (int c = 0; c < KCHUNKS; c++) {
                CP_WAIT2();
                __syncthreads();

                const uint32_t aT = sbA + (c & 3) * A_STAGE;
                const uint32_t bT = sbB + bslot * B_STAGE;

                #pragma unroll
                for (int kk = 0; kk < 4; kk++) {
                    uint32_t a0[4], a1[4];
                    ldsm4(a0, aT + aOff0 + ((((kk << 1) | akh) ^ a7_0) << 4));
                    ldsm4(a1, aT + aOff1 + ((((kk << 1) | akh) ^ a7_1) << 4));
                    #pragma unroll
                    for (int s = 0; s < NSPLIT; s++) {
                        uint32_t bb[4];
                        ldsm4(bb, bT + s * A_STAGE + bOff + ((((kk << 1) | bkh) ^ b7) << 4));
                        mma16816(acc[0][0], a0, bb[0], bb[1]);
                        mma16816(acc[0][1], a0, bb[2], bb[3]);
                        mma16816(acc[1][0], a1, bb[0], bb[1]);
                        mma16816(acc[1][1], a1, bb[2], bb[3]);
                    }
                }

                // prefetch: A distance 3 (flag-gated), B distance 5 (continuous
                // mod-6 ring — near step end this preloads next step's B)
                const int an = c + 3;
                if (an < KCHUNKS) {
                    wait_flag(mflags + an, (unsigned)t);   // producer done step t-1
                    load_tile256(sbA + (an & 3) * A_STAGE, gA + (size_t)an * 128);
                }
                int bn = c + 5; if (bn >= KCHUNKS) bn -= KCHUNKS;
                int ps = bslot + 5; if (ps >= NB_STAGE) ps -= NB_STAGE;
                load_B(sbB + ps * B_STAGE, gB, bn, SSTR);
                CP_COMMIT();

                bslot = (bslot + 1 == NB_STAGE) ? 0 : bslot + 1;
            }
        }

        __syncthreads();

        // ---- fused LIF epilogue (V in registers, Win in registers) ----
        const float* xt = x + (size_t)t * BATCH * 3;
        float*         outT = out + (size_t)t * BATCH * RES;
        __nv_bfloat16* Sw   = g_S + (size_t)(t & 1) * BATCH * RES;

        #pragma unroll
        for (int mi = 0; mi < 2; mi++) {
            #pragma unroll
            for (int r = 0; r < 2; r++) {
                const int b = m0 + wm * 32 + mi * 16 + r * 8 + lr;
                const float x0 = xt[b * 3 + 0];
                const float x1 = xt[b * 3 + 1];
                const float x2 = xt[b * 3 + 2];
                #pragma unroll
                for (int nt = 0; nt < 2; nt++) {
                    const int nl = wn * 16 + nt * 8 + lc * 2;
                    const size_t vi = (size_t)b * RES + n0 + nl;
                    const float inj0 = x0 * wv[nt * 2 + 0][0] + x1 * wv[nt * 2 + 0][1] + x2 * wv[nt * 2 + 0][2];
                    const float inj1 = x0 * wv[nt * 2 + 1][0] + x1 * wv[nt * 2 + 1][1] + x2 * wv[nt * 2 + 1][2];
                    const float y0 = BETA * V[mi][r][nt][0] + inj0 + acc[mi][nt][r * 2 + 0];
                    const float y1 = BETA * V[mi][r][nt][1] + inj1 + acc[mi][nt][r * 2 + 1];
                    const float s0 = (y0 >= THRESH) ? 1.0f : 0.0f;
                    const float s1 = (y1 >= THRESH) ? 1.0f : 0.0f;
                    V[mi][r][nt][0] = (y0 >= THRESH) ? 0.0f : y0;
                    V[mi][r][nt][1] = (y1 >= THRESH) ? 0.0f : y1;
                    float2 sp; sp.x = s0; sp.y = s1;
                    *(float2*)&outT[vi] = sp;
                    __nv_bfloat162 sb2;
                    sb2.x = __float2bfloat16(s0);
                    sb2.y = __float2bfloat16(s1);
                    *(__nv_bfloat162*)&Sw[vi] = sb2;
                }
            }
        }

        // publish this tile's spikes: all stores done -> fence -> flag++
        __syncthreads();
        if (tid == 0) {
            __threadfence();
            atomicAdd(myflag, 1u);
        }

        if (t < T_STEPS - 1) {
            // preload next step's A chunks 0..2 (flag-gated per producer)
            const char* gA2 = (const char*)g_S
                + (size_t)(t & 1) * BATCH * RES * 2 + (size_t)m0 * ROW_BYTES;
            #pragma unroll
            for (int p = 0; p < 3; p++) {
                wait_flag(mflags + p, (unsigned)(t + 1));
                load_tile256(sbA + p * A_STAGE, gA2 + (size_t)p * 128);
                CP_COMMIT();
            }
        }
    }
}

// ---------------------------------------------------------------------------
__global__ void __launch_bounds__(256)
logits_kernel(const float* __restrict__ spk,
              const float* __restrict__ Wout,
              float* __restrict__ logits)
{
    const int b = blockIdx.x;
    const int tid = threadIdx.x;
    float p0 = 0.0f, p1 = 0.0f;
    for (int r = tid; r < RES; r += 256) {
        float s = 0.0f;
        #pragma unroll
        for (int tt = 0; tt < 10; tt++)
            s += spk[((size_t)(T_STEPS - 10 + tt) * BATCH + b) * RES + r];
        s *= 0.1f;
        p0 = fmaf(s, Wout[r], p0);
        p1 = fmaf(s, Wout[RES + r], p1);
    }
    __shared__ float sh0[256];
    __shared__ float sh1[256];
    sh0[tid] = p0; sh1[tid] = p1;
    __syncthreads();
    for (int off = 128; off > 0; off >>= 1) {
        if (tid < off) { sh0[tid] += sh0[tid + off]; sh1[tid] += sh1[tid + off]; }
        __syncthreads();
    }
    if (tid == 0) {
        logits[b * OUTD + 0] = sh0[0];
        logits[b * OUTD + 1] = sh1[0];
    }
}

// ---------------------------------------------------------------------------
extern "C" void kernel_launch(void* const* d_in, const int* in_sizes, int n_in,
                              void* d_out, int out_size)
{
    const float* x    = (const float*)d_in[0];  // [200, 256, 3]
    const float* W    = (const float*)d_in[1];  // [2048, 2048]
    const float* Win  = (const float*)d_in[2];  // [2048, 3]
    const float* Wout = (const float*)d_in[3];  // [2, 2048]
    float* out = (float*)d_out;                 // spk [200*256*2048] | logits [256*2]

    cudaFuncSetAttribute(reservoir_kernel, cudaFuncAttributeMaxDynamicSharedMemorySize, SMEM_DYN);

    init_kernel<<<1, 128>>>();
    split_kernel<<<dim3(RES / 32, RES / 32), dim3(32, 8)>>>(W);

    dim3 grid(RES / BN, BATCH / BM);  // (32, 4) = 128 CTAs, all co-resident
    reservoir_kernel<<<grid, 256, SMEM_DYN>>>(x, Win, out);

    logits_kernel<<<BATCH, 256>>>(out, Wout, out + SPK_ELEMS);
}

// round 10
// speedup vs baseline: 1.7653x; 1.7653x over previous
#include <cuda_runtime.h>
#include <cuda_bf16.h>
#include <cstdint>

// ---------------- problem constants ----------------
#define T_STEPS 200
#define BATCH   256
#define RES     2048
#define OUTD    2
#define BETA    0.9f
#define THRESH  1.0f
#define SPK_ELEMS ((size_t)T_STEPS * BATCH * RES)
#define NSPLIT 3

// GEMM tiling: CTA 64(M) x 64(N), k-chunk 64, 256 threads (8 warps, 2x4),
// warp tile 32(M) x 16(N), mma.sync m16n8k16 bf16.
// Persistent kernel: one CTA/SM, split-phase grid barrier between steps,
// V in registers, fp32 spike stores deferred into the barrier window.
// Split rings: A 4 x 8KB, B 6 x 24KB (B static across steps -> prefetched
// ACROSS the grid barrier with a continuous mod-6 slot counter).
#define BM 64
#define BN 64
#define BK 64
#define KCHUNKS (RES / BK)              // 32
#define ROW_BYTES 4096                  // 2048 bf16 per row
#define A_STAGE 8192
#define B_STAGE 24576
#define NB_STAGE 6
#define SMEM_DYN (4 * A_STAGE + NB_STAGE * B_STAGE)   // 180224
#define NBLK 128                        // grid size (<= SM count, co-resident)

// ---------------- device state ----------------
__device__ __nv_bfloat16 g_S[2 * BATCH * RES];                    // spike double buffer
__device__ __nv_bfloat16 g_W3[(size_t)NSPLIT * RES * RES];        // split W, [s][n][k]
__device__ unsigned g_bar_arrive;
__device__ unsigned g_bar_gen;

// ---------------- helpers ----------------
__device__ __forceinline__ uint32_t smem_u32(const void* p) {
    uint32_t a;
    asm("{ .reg .u64 t; cvta.to.shared.u64 t, %1; cvt.u32.u64 %0, t; }" : "=r"(a) : "l"(p));
    return a;
}

__device__ __forceinline__ void ldsm4(uint32_t* r, uint32_t addr) {
    asm volatile("ldmatrix.sync.aligned.m8n8.x4.shared.b16 {%0,%1,%2,%3}, [%4];"
                 : "=r"(r[0]), "=r"(r[1]), "=r"(r[2]), "=r"(r[3]) : "r"(addr));
}

__device__ __forceinline__ void mma16816(float* c, const uint32_t* a, uint32_t b0, uint32_t b1) {
    asm volatile("mma.sync.aligned.m16n8k16.row.col.f32.bf16.bf16.f32 "
                 "{%0,%1,%2,%3}, {%4,%5,%6,%7}, {%8,%9}, {%0,%1,%2,%3};"
                 : "+f"(c[0]), "+f"(c[1]), "+f"(c[2]), "+f"(c[3])
                 : "r"(a[0]), "r"(a[1]), "r"(a[2]), "r"(a[3]), "r"(b0), "r"(b1));
}

#define CP_COMMIT() asm volatile("cp.async.commit_group;" ::: "memory")
#define CP_WAIT2()  asm volatile("cp.async.wait_group 2;" ::: "memory")

// Split-phase grid barrier. Safe: grid = 128 CTAs, 1/SM, all co-resident.
// Call bar_arrive AFTER a __syncthreads covering the stores to publish.
__device__ __forceinline__ void bar_arrive(unsigned* s_gen) {
    if (threadIdx.x == 0) {
        unsigned gen;
        asm volatile("ld.acquire.gpu.global.u32 %0, [%1];" : "=r"(gen) : "l"(&g_bar_gen));
        *s_gen = gen;
        unsigned prev;
        asm volatile("atom.add.release.gpu.global.u32 %0, [%1], %2;"
                     : "=r"(prev) : "l"(&g_bar_arrive), "r"(1u));
        if (prev == NBLK - 1) {
            asm volatile("st.relaxed.gpu.global.u32 [%0], %1;" :: "l"(&g_bar_arrive), "r"(0u));
            asm volatile("red.release.gpu.global.add.u32 [%0], %1;" :: "l"(&g_bar_gen), "r"(1u));
        }
    }
}
__device__ __forceinline__ void bar_wait(const unsigned* s_gen) {
    if (threadIdx.x == 0) {
        const unsigned gen = *s_gen;
        unsigned cur;
        do {
            asm volatile("ld.acquire.gpu.global.u32 %0, [%1];" : "=r"(cur) : "l"(&g_bar_gen));
        } while (cur == gen);
    }
    __syncthreads();
}

// 64x64 bf16 tile (8KB): rows of 128B = 8 x 16B chunks, chunk ^= row%8 swizzle.
// 256 threads, 2 x 16B cp.async each.
__device__ __forceinline__ void load_tile256(uint32_t sbase, const char* g) {
    const int tid = threadIdx.x;
    #pragma unroll
    for (int i = 0; i < 2; i++) {
        int c = tid + i * 256;
        int row = c >> 3, ch = c & 7;
        uint32_t dst = sbase + row * 128 + ((ch ^ (row & 7)) << 4);
        const char* src = g + (size_t)row * ROW_BYTES + ch * 16;
        asm volatile("cp.async.cg.shared.global [%0], [%1], 16;" :: "r"(dst), "l"(src));
    }
}

// load B for one chunk (3 split tiles) into one B stage
__device__ __forceinline__ void load_B(uint32_t stage, const char* gB, int chunk, size_t sstr) {
    #pragma unroll
    for (int s = 0; s < NSPLIT; s++)
        load_tile256(stage + s * A_STAGE, gB + (size_t)s * sstr + (size_t)chunk * 128);
}

// ---------------------------------------------------------------------------
__global__ void init_kernel() {
    if (threadIdx.x == 0) { g_bar_arrive = 0u; g_bar_gen = 0u; }
}

// split+transpose W: g_W3[s][n][k] = bf16 split s of W[k][n]
__global__ void split_kernel(const float* __restrict__ W) {
    __shared__ float sh[32][33];
    const int k0 = blockIdx.x * 32;
    const int n0 = blockIdx.y * 32;
    const int tx = threadIdx.x;
    const int ty = threadIdx.y;
    #pragma unroll
    for (int i = ty; i < 32; i += 8)
        sh[i][tx] = W[(size_t)(k0 + i) * RES + n0 + tx];
    __syncthreads();
    #pragma unroll
    for (int i = ty; i < 32; i += 8) {
        float w = sh[tx][i];  // = W[k0+tx][n0+i]
        __nv_bfloat16 b0 = __float2bfloat16(w);
        float r1 = w - __bfloat162float(b0);
        __nv_bfloat16 b1 = __float2bfloat16(r1);
        float r2 = r1 - __bfloat162float(b1);
        __nv_bfloat16 b2 = __float2bfloat16(r2);
        size_t o = (size_t)(n0 + i) * RES + k0 + tx;
        g_W3[o]                         = b0;
        g_W3[(size_t)RES * RES + o]     = b1;
        g_W3[(size_t)2 * RES * RES + o] = b2;
    }
}

// ---------------------------------------------------------------------------
// persistent reservoir kernel: all 200 timesteps, grid barrier between steps.
// ---------------------------------------------------------------------------
__global__ void __launch_bounds__(256, 1)
reservoir_kernel(const float* __restrict__ x,
                 const float* __restrict__ Win,
                 float* __restrict__ out)
{
    extern __shared__ __align__(128) char dsm[];
    __shared__ float sX[BATCH * 3];
    __shared__ unsigned s_gen;

    const int tid  = threadIdx.x;
    const int lane = tid & 31;
    const int warp = tid >> 5;
    const int n0 = blockIdx.x * BN;
    const int m0 = blockIdx.y * BM;
    const int wm = warp >> 2;        // 0..1 -> m offset *32
    const int wn = warp & 3;         // 0..3 -> n offset *16
    const int grp  = lane >> 3;      // ldmatrix address group
    const int lrow = lane & 7;
    const int lr = lane >> 2;        // mma frag row
    const int lc = lane & 3;         // mma frag col pair

    const uint32_t sbA = smem_u32(dsm);
    const uint32_t sbB = sbA + 4 * A_STAGE;
    const char* gB = (const char*)g_W3 + (size_t)n0 * ROW_BYTES;
    const size_t SSTR = (size_t)RES * RES * 2;   // split stride (bytes)

    // this thread's 4 epilogue n-columns: wn*16 + nt*8 + lc*2 + {0,1}
    float wv[4][3];
    #pragma unroll
    for (int nt = 0; nt < 2; nt++)
        #pragma unroll
        for (int q = 0; q < 2; q++) {
            const int nl = wn * 16 + nt * 8 + lc * 2 + q;
            wv[nt * 2 + q][0] = Win[(n0 + nl) * 3 + 0];
            wv[nt * 2 + q][1] = Win[(n0 + nl) * 3 + 1];
            wv[nt * 2 + q][2] = Win[(n0 + nl) * 3 + 2];
        }

    // ldmatrix per-thread row bases (constant across steps)
    const int rowA0 = wm * 32 + (grp & 1) * 8 + lrow;
    const int rowA1 = rowA0 + 16;
    const int rowB  = wn * 16 + (grp >> 1) * 8 + lrow;
    const uint32_t aOff0 = rowA0 * 128, aOff1 = rowA1 * 128, bOff = rowB * 128;
    const int a7_0 = rowA0 & 7, a7_1 = rowA1 & 7, b7 = rowB & 7;
    const int akh = grp >> 1, bkh = grp & 1;

    // membrane potential in registers: V[mi][r][nt][2]
    float V[2][2][2][2];
    #pragma unroll
    for (int a = 0; a < 2; a++)
        #pragma unroll
        for (int b = 0; b < 2; b++)
            #pragma unroll
            for (int c = 0; c < 2; c++)
                V[a][b][c][0] = V[a][b][c][1] = 0.0f;

    // preload B chunks 0..4 into B slots 0..4 (5 groups)
    #pragma unroll
    for (int p = 0; p < 5; p++) {
        load_B(sbB + p * B_STAGE, gB, p, SSTR);
        CP_COMMIT();
    }

    int bslot = 0;  // continuous B ring cursor (mod 6)

    #pragma unroll 1
    for (int t = 0; t < T_STEPS; t++) {
        float acc[2][2][4];
        #pragma unroll
        for (int a = 0; a < 2; a++)
            #pragma unroll
            for (int b = 0; b < 2; b++)
                #pragma unroll
                for (int c = 0; c < 4; c++) acc[a][b][c] = 0.0f;

        // stage x_t into smem (LDG issued now; hidden behind the mainloop)
        {
            const float* xt = x + (size_t)t * BATCH * 3;
            #pragma unroll
            for (int i = tid; i < BATCH * 3; i += 256) sX[i] = xt[i];
        }

        if (t > 0) {
            const char* gA = (const char*)g_S
                + (size_t)((t + 1) & 1) * BATCH * RES * 2 + (size_t)m0 * ROW_BYTES;

            #pragma unroll 1
            for (int c = 0; c < KCHUNKS; c++) {
                CP_WAIT2();
                __syncthreads();

                const uint32_t aT = sbA + (c & 3) * A_STAGE;
                const uint32_t bT = sbB + bslot * B_STAGE;

                #pragma unroll
                for (int kk = 0; kk < 4; kk++) {
                    uint32_t a0[4], a1[4];
                    ldsm4(a0, aT + aOff0 + ((((kk << 1) | akh) ^ a7_0) << 4));
                    ldsm4(a1, aT + aOff1 + ((((kk << 1) | akh) ^ a7_1) << 4));
                    #pragma unroll
                    for (int s = 0; s < NSPLIT; s++) {
                        uint32_t bb[4];
                        ldsm4(bb, bT + s * A_STAGE + bOff + ((((kk << 1) | bkh) ^ b7) << 4));
                        mma16816(acc[0][0], a0, bb[0], bb[1]);
                        mma16816(acc[0][1], a0, bb[2], bb[3]);
                        mma16816(acc[1][0], a1, bb[0], bb[1]);
                        mma16816(acc[1][1], a1, bb[2], bb[3]);
                    }
                }

                // prefetch: A distance 3 (same step only), B distance 5
                // (continuous — at c>=27 this preloads NEXT step's B chunks)
                const int an = c + 3;
                if (an < KCHUNKS)
                    load_tile256(sbA + (an & 3) * A_STAGE, gA + (size_t)an * 128);
                int bn = c + 5; if (bn >= KCHUNKS) bn -= KCHUNKS;
                int ps = bslot + 5; if (ps >= NB_STAGE) ps -= NB_STAGE;
                load_B(sbB + ps * B_STAGE, gB, bn, SSTR);
                CP_COMMIT();

                bslot = (bslot + 1 == NB_STAGE) ? 0 : bslot + 1;
            }
        }

        __syncthreads();  // mainloop done; sX visible

        // ---- fused LIF epilogue: compute spikes, store bf16 g_S only ----
        __nv_bfloat16* Sw = g_S + (size_t)(t & 1) * BATCH * RES;
        float sreg[2][2][2][2];   // fp32 spikes kept for deferred out store

        #pragma unroll
        for (int mi = 0; mi < 2; mi++) {
            #pragma unroll
            for (int r = 0; r < 2; r++) {
                const int b = m0 + wm * 32 + mi * 16 + r * 8 + lr;
                const float x0 = sX[b * 3 + 0];
                const float x1 = sX[b * 3 + 1];
                const float x2 = sX[b * 3 + 2];
                #pragma unroll
                for (int nt = 0; nt < 2; nt++) {
                    const int nl = wn * 16 + nt * 8 + lc * 2;
                    const size_t vi = (size_t)b * RES + n0 + nl;
                    const float inj0 = x0 * wv[nt * 2 + 0][0] + x1 * wv[nt * 2 + 0][1] + x2 * wv[nt * 2 + 0][2];
                    const float inj1 = x0 * wv[nt * 2 + 1][0] + x1 * wv[nt * 2 + 1][1] + x2 * wv[nt * 2 + 1][2];
                    const float y0 = BETA * V[mi][r][nt][0] + inj0 + acc[mi][nt][r * 2 + 0];
                    const float y1 = BETA * V[mi][r][nt][1] + inj1 + acc[mi][nt][r * 2 + 1];
                    const float s0 = (y0 >= THRESH) ? 1.0f : 0.0f;
                    const float s1 = (y1 >= THRESH) ? 1.0f : 0.0f;
                    V[mi][r][nt][0] = (y0 >= THRESH) ? 0.0f : y0;
                    V[mi][r][nt][1] = (y1 >= THRESH) ? 0.0f : y1;
                    sreg[mi][r][nt][0] = s0;
                    sreg[mi][r][nt][1] = s1;
                    __nv_bfloat162 sb2;
                    sb2.x = __float2bfloat16(s0);
                    sb2.y = __float2bfloat16(s1);
                    *(__nv_bfloat162*)&Sw[vi] = sb2;
                }
            }
        }

        // publish bf16 spikes to peers, then fill the barrier window with the
        // fp32 spike-record stores (consumed only by the final logits kernel)
        __syncthreads();
        const bool more = (t < T_STEPS - 1);
        if (more) bar_arrive(&s_gen);

        {
            float* outT = out + (size_t)t * BATCH * RES;
            #pragma unroll
            for (int mi = 0; mi < 2; mi++) {
                #pragma unroll
                for (int r = 0; r < 2; r++) {
                    const int b = m0 + wm * 32 + mi * 16 + r * 8 + lr;
                    #pragma unroll
                    for (int nt = 0; nt < 2; nt++) {
                        const int nl = wn * 16 + nt * 8 + lc * 2;
                        const size_t vi = (size_t)b * RES + n0 + nl;
                        float2 sp;
                        sp.x = sreg[mi][r][nt][0];
                        sp.y = sreg[mi][r][nt][1];
                        *(float2*)&outT[vi] = sp;
                    }
                }
            }
        }

        if (more) {
            bar_wait(&s_gen);
            // post-barrier: only A chunks 0..2 stand before the first MMA
            const char* gA2 = (const char*)g_S
                + (size_t)(t & 1) * BATCH * RES * 2 + (size_t)m0 * ROW_BYTES;
            #pragma unroll
            for (int p = 0; p < 3; p++) {
                load_tile256(sbA + p * A_STAGE, gA2 + (size_t)p * 128);
                CP_COMMIT();
            }
        }
    }
}

// ---------------------------------------------------------------------------
__global__ void __launch_bounds__(256)
logits_kernel(const float* __restrict__ spk,
              const float* __restrict__ Wout,
              float* __restrict__ logits)
{
    const int b = blockIdx.x;
    const int tid = threadIdx.x;
    float p0 = 0.0f, p1 = 0.0f;
    for (int r = tid; r < RES; r += 256) {
        float s = 0.0f;
        #pragma unroll
        for (int tt = 0; tt < 10; tt++)
            s += spk[((size_t)(T_STEPS - 10 + tt) * BATCH + b) * RES + r];
        s *= 0.1f;
        p0 = fmaf(s, Wout[r], p0);
        p1 = fmaf(s, Wout[RES + r], p1);
    }
    __shared__ float sh0[256];
    __shared__ float sh1[256];
    sh0[tid] = p0; sh1[tid] = p1;
    __syncthreads();
    for (int off = 128; off > 0; off >>= 1) {
        if (tid < off) { sh0[tid] += sh0[tid + off]; sh1[tid] += sh1[tid + off]; }
        __syncthreads();
    }
    if (tid == 0) {
        logits[b * OUTD + 0] = sh0[0];
        logits[b * OUTD + 1] = sh1[0];
    }
}

// ---------------------------------------------------------------------------
extern "C" void kernel_launch(void* const* d_in, const int* in_sizes, int n_in,
                              void* d_out, int out_size)
{
    const float* x    = (const float*)d_in[0];  // [200, 256, 3]
    const float* W    = (const float*)d_in[1];  // [2048, 2048]
    const float* Win  = (const float*)d_in[2];  // [2048, 3]
    const float* Wout = (const float*)d_in[3];  // [2, 2048]
    float* out = (float*)d_out;                 // spk [200*256*2048] | logits [256*2]

    cudaFuncSetAttribute(reservoir_kernel, cudaFuncAttributeMaxDynamicSharedMemorySize, SMEM_DYN);

    init_kernel<<<1, 32>>>();
    split_kernel<<<dim3(RES / 32, RES / 32), dim3(32, 8)>>>(W);

    dim3 grid(RES / BN, BATCH / BM);  // (32, 4) = 128 CTAs, all co-resident
    reservoir_kernel<<<grid, 256, SMEM_DYN>>>(x, Win, out);

    logits_kernel<<<BATCH, 256>>>(out, Wout, out + SPK_ELEMS);
}

// round 11
// speedup vs baseline: 1.7670x; 1.0009x over previous
#include <cuda_runtime.h>
#include <cuda_bf16.h>
#include <cstdint>

// ---------------- problem constants ----------------
#define T_STEPS 200
#define BATCH   256
#define RES     2048
#define OUTD    2
#define BETA    0.9f
#define THRESH  1.0f
#define SPK_ELEMS ((size_t)T_STEPS * BATCH * RES)
#define NSPLIT 3

// GEMM tiling: CTA 64(M) x 64(N), k-chunk 64, 256 threads (8 warps, 2x4),
// warp tile 32(M) x 16(N), mma.sync m16n8k16 bf16.
// Persistent kernel: one CTA/SM, split-phase grid barrier between steps,
// V in registers, fp32 spike stores deferred into the barrier window.
// Split rings: A 4 x 8KB, B 6 x 24KB (B static across steps -> prefetched
// ACROSS the grid barrier with a continuous mod-6 slot counter).
#define BM 64
#define BN 64
#define BK 64
#define KCHUNKS (RES / BK)              // 32
#define ROW_BYTES 4096                  // 2048 bf16 per row
#define A_STAGE 8192
#define B_STAGE 24576
#define NB_STAGE 6
#define SMEM_DYN (4 * A_STAGE + NB_STAGE * B_STAGE)   // 180224
#define NBLK 128                        // grid size (<= SM count, co-resident)

// ---------------- device state ----------------
__device__ __nv_bfloat16 g_S[2 * BATCH * RES];                    // spike double buffer
__device__ __nv_bfloat16 g_W3[(size_t)NSPLIT * RES * RES];        // split W, [s][n][k]
__device__ unsigned g_bar_arrive;
__device__ unsigned g_bar_gen;

// ---------------- helpers ----------------
__device__ __forceinline__ uint32_t smem_u32(const void* p) {
    uint32_t a;
    asm("{ .reg .u64 t; cvta.to.shared.u64 t, %1; cvt.u32.u64 %0, t; }" : "=r"(a) : "l"(p));
    return a;
}

__device__ __forceinline__ void ldsm4(uint32_t* r, uint32_t addr) {
    asm volatile("ldmatrix.sync.aligned.m8n8.x4.shared.b16 {%0,%1,%2,%3}, [%4];"
                 : "=r"(r[0]), "=r"(r[1]), "=r"(r[2]), "=r"(r[3]) : "r"(addr));
}

__device__ __forceinline__ void mma16816(float* c, const uint32_t* a, uint32_t b0, uint32_t b1) {
    asm volatile("mma.sync.aligned.m16n8k16.row.col.f32.bf16.bf16.f32 "
                 "{%0,%1,%2,%3}, {%4,%5,%6,%7}, {%8,%9}, {%0,%1,%2,%3};"
                 : "+f"(c[0]), "+f"(c[1]), "+f"(c[2]), "+f"(c[3])
                 : "r"(a[0]), "r"(a[1]), "r"(a[2]), "r"(a[3]), "r"(b0), "r"(b1));
}

#define CP_COMMIT() asm volatile("cp.async.commit_group;" ::: "memory")
#define CP_WAIT2()  asm volatile("cp.async.wait_group 2;" ::: "memory")

// Split-phase grid barrier. Safe: grid = 128 CTAs, 1/SM, all co-resident.
// Call bar_arrive AFTER a __syncthreads covering the stores to publish.
__device__ __forceinline__ void bar_arrive(unsigned* s_gen) {
    if (threadIdx.x == 0) {
        unsigned gen;
        asm volatile("ld.acquire.gpu.global.u32 %0, [%1];" : "=r"(gen) : "l"(&g_bar_gen));
        *s_gen = gen;
        unsigned prev;
        asm volatile("atom.add.release.gpu.global.u32 %0, [%1], %2;"
                     : "=r"(prev) : "l"(&g_bar_arrive), "r"(1u));
        if (prev == NBLK - 1) {
            asm volatile("st.relaxed.gpu.global.u32 [%0], %1;" :: "l"(&g_bar_arrive), "r"(0u));
            asm volatile("red.release.gpu.global.add.u32 [%0], %1;" :: "l"(&g_bar_gen), "r"(1u));
        }
    }
}
__device__ __forceinline__ void bar_wait(const unsigned* s_gen) {
    if (threadIdx.x == 0) {
        const unsigned gen = *s_gen;
        unsigned cur;
        do {
            asm volatile("ld.acquire.gpu.global.u32 %0, [%1];" : "=r"(cur) : "l"(&g_bar_gen));
        } while (cur == gen);
    }
    __syncthreads();
}

// 64x64 bf16 tile (8KB): rows of 128B = 8 x 16B chunks, chunk ^= row%8 swizzle.
// 256 threads, 2 x 16B cp.async each.
__device__ __forceinline__ void load_tile256(uint32_t sbase, const char* g) {
    const int tid = threadIdx.x;
    #pragma unroll
    for (int i = 0; i < 2; i++) {
        int c = tid + i * 256;
        int row = c >> 3, ch = c & 7;
        uint32_t dst = sbase + row * 128 + ((ch ^ (row & 7)) << 4);
        const char* src = g + (size_t)row * ROW_BYTES + ch * 16;
        asm volatile("cp.async.cg.shared.global [%0], [%1], 16;" :: "r"(dst), "l"(src));
    }
}

// load B for one chunk (3 split tiles) into one B stage
__device__ __forceinline__ void load_B(uint32_t stage, const char* gB, int chunk, size_t sstr) {
    #pragma unroll
    for (int s = 0; s < NSPLIT; s++)
        load_tile256(stage + s * A_STAGE, gB + (size_t)s * sstr + (size_t)chunk * 128);
}

// ---------------------------------------------------------------------------
__global__ void init_kernel() {
    if (threadIdx.x == 0) { g_bar_arrive = 0u; g_bar_gen = 0u; }
}

// split+transpose W: g_W3[s][n][k] = bf16 split s of W[k][n]
__global__ void split_kernel(const float* __restrict__ W) {
    __shared__ float sh[32][33];
    const int k0 = blockIdx.x * 32;
    const int n0 = blockIdx.y * 32;
    const int tx = threadIdx.x;
    const int ty = threadIdx.y;
    #pragma unroll
    for (int i = ty; i < 32; i += 8)
        sh[i][tx] = W[(size_t)(k0 + i) * RES + n0 + tx];
    __syncthreads();
    #pragma unroll
    for (int i = ty; i < 32; i += 8) {
        float w = sh[tx][i];  // = W[k0+tx][n0+i]
        __nv_bfloat16 b0 = __float2bfloat16(w);
        float r1 = w - __bfloat162float(b0);
        __nv_bfloat16 b1 = __float2bfloat16(r1);
        float r2 = r1 - __bfloat162float(b1);
        __nv_bfloat16 b2 = __float2bfloat16(r2);
        size_t o = (size_t)(n0 + i) * RES + k0 + tx;
        g_W3[o]                         = b0;
        g_W3[(size_t)RES * RES + o]     = b1;
        g_W3[(size_t)2 * RES * RES + o] = b2;
    }
}

// ---------------------------------------------------------------------------
// persistent reservoir kernel: all 200 timesteps, grid barrier between steps.
// ---------------------------------------------------------------------------
__global__ void __launch_bounds__(256, 1)
reservoir_kernel(const float* __restrict__ x,
                 const float* __restrict__ Win,
                 float* __restrict__ out)
{
    extern __shared__ __align__(128) char dsm[];
    __shared__ float sX[BATCH * 3];
    __shared__ unsigned s_gen;

    const int tid  = threadIdx.x;
    const int lane = tid & 31;
    const int warp = tid >> 5;
    const int n0 = blockIdx.x * BN;
    const int m0 = blockIdx.y * BM;
    const int wm = warp >> 2;        // 0..1 -> m offset *32
    const int wn = warp & 3;         // 0..3 -> n offset *16
    const int grp  = lane >> 3;      // ldmatrix address group
    const int lrow = lane & 7;
    const int lr = lane >> 2;        // mma frag row
    const int lc = lane & 3;         // mma frag col pair

    const uint32_t sbA = smem_u32(dsm);
    const uint32_t sbB = sbA + 4 * A_STAGE;
    const char* gB = (const char*)g_W3 + (size_t)n0 * ROW_BYTES;
    const size_t SSTR = (size_t)RES * RES * 2;   // split stride (bytes)

    // this thread's 4 epilogue n-columns: wn*16 + nt*8 + lc*2 + {0,1}
    float wv[4][3];
    #pragma unroll
    for (int nt = 0; nt < 2; nt++)
        #pragma unroll
        for (int q = 0; q < 2; q++) {
            const int nl = wn * 16 + nt * 8 + lc * 2 + q;
            wv[nt * 2 + q][0] = Win[(n0 + nl) * 3 + 0];
            wv[nt * 2 + q][1] = Win[(n0 + nl) * 3 + 1];
            wv[nt * 2 + q][2] = Win[(n0 + nl) * 3 + 2];
        }

    // ldmatrix per-thread row bases (constant across steps)
    const int rowA0 = wm * 32 + (grp & 1) * 8 + lrow;
    const int rowA1 = rowA0 + 16;
    const int rowB  = wn * 16 + (grp >> 1) * 8 + lrow;
    const uint32_t aOff0 = rowA0 * 128, aOff1 = rowA1 * 128, bOff = rowB * 128;
    const int a7_0 = rowA0 & 7, a7_1 = rowA1 & 7, b7 = rowB & 7;
    const int akh = grp >> 1, bkh = grp & 1;

    // membrane potential in registers: V[mi][r][nt][2]
    float V[2][2][2][2];
    #pragma unroll
    for (int a = 0; a < 2; a++)
        #pragma unroll
        for (int b = 0; b < 2; b++)
            #pragma unroll
            for (int c = 0; c < 2; c++)
                V[a][b][c][0] = V[a][b][c][1] = 0.0f;

    // preload B chunks 0..4 into B slots 0..4 (5 groups)
    #pragma unroll
    for (int p = 0; p < 5; p++) {
        load_B(sbB + p * B_STAGE, gB, p, SSTR);
        CP_COMMIT();
    }

    int bslot = 0;  // continuous B ring cursor (mod 6)

    #pragma unroll 1
    for (int t = 0; t < T_STEPS; t++) {
        float acc[2][2][4];
        #pragma unroll
        for (int a = 0; a < 2; a++)
            #pragma unroll
            for (int b = 0; b < 2; b++)
                #pragma unroll
                for (int c = 0; c < 4; c++) acc[a][b][c] = 0.0f;

        // stage x_t into smem (LDG issued now; hidden behind the mainloop)
        {
            const float* xt = x + (size_t)t * BATCH * 3;
            #pragma unroll
            for (int i = tid; i < BATCH * 3; i += 256) sX[i] = xt[i];
        }

        if (t > 0) {
            const char* gA = (const char*)g_S
                + (size_t)((t + 1) & 1) * BATCH * RES * 2 + (size_t)m0 * ROW_BYTES;

            #pragma unroll 1
            for (int c = 0; c < KCHUNKS; c++) {
                CP_WAIT2();
                __syncthreads();

                const uint32_t aT = sbA + (c & 3) * A_STAGE;
                const uint32_t bT = sbB + bslot * B_STAGE;

                #pragma unroll
                for (int kk = 0; kk < 4; kk++) {
                    uint32_t a0[4], a1[4];
                    ldsm4(a0, aT + aOff0 + ((((kk << 1) | akh) ^ a7_0) << 4));
                    ldsm4(a1, aT + aOff1 + ((((kk << 1) | akh) ^ a7_1) << 4));
                    #pragma unroll
                    for (int s = 0; s < NSPLIT; s++) {
                        uint32_t bb[4];
                        ldsm4(bb, bT + s * A_STAGE + bOff + ((((kk << 1) | bkh) ^ b7) << 4));
                        mma16816(acc[0][0], a0, bb[0], bb[1]);
                        mma16816(acc[0][1], a0, bb[2], bb[3]);
                        mma16816(acc[1][0], a1, bb[0], bb[1]);
                        mma16816(acc[1][1], a1, bb[2], bb[3]);
                    }
                }

                // prefetch: A distance 3 (same step only), B distance 5
                // (continuous — at c>=27 this preloads NEXT step's B chunks)
                const int an = c + 3;
                if (an < KCHUNKS)
                    load_tile256(sbA + (an & 3) * A_STAGE, gA + (size_t)an * 128);
                int bn = c + 5; if (bn >= KCHUNKS) bn -= KCHUNKS;
                int ps = bslot + 5; if (ps >= NB_STAGE) ps -= NB_STAGE;
                load_B(sbB + ps * B_STAGE, gB, bn, SSTR);
                CP_COMMIT();

                bslot = (bslot + 1 == NB_STAGE) ? 0 : bslot + 1;
            }
        }

        __syncthreads();  // mainloop done; sX visible

        // ---- fused LIF epilogue: compute spikes, store bf16 g_S only ----
        __nv_bfloat16* Sw = g_S + (size_t)(t & 1) * BATCH * RES;
        float sreg[2][2][2][2];   // fp32 spikes kept for deferred out store

        #pragma unroll
        for (int mi = 0; mi < 2; mi++) {
            #pragma unroll
            for (int r = 0; r < 2; r++) {
                const int b = m0 + wm * 32 + mi * 16 + r * 8 + lr;
                const float x0 = sX[b * 3 + 0];
                const float x1 = sX[b * 3 + 1];
                const float x2 = sX[b * 3 + 2];
                #pragma unroll
                for (int nt = 0; nt < 2; nt++) {
                    const int nl = wn * 16 + nt * 8 + lc * 2;
                    const size_t vi = (size_t)b * RES + n0 + nl;
                    const float inj0 = x0 * wv[nt * 2 + 0][0] + x1 * wv[nt * 2 + 0][1] + x2 * wv[nt * 2 + 0][2];
                    const float inj1 = x0 * wv[nt * 2 + 1][0] + x1 * wv[nt * 2 + 1][1] + x2 * wv[nt * 2 + 1][2];
                    const float y0 = BETA * V[mi][r][nt][0] + inj0 + acc[mi][nt][r * 2 + 0];
                    const float y1 = BETA * V[mi][r][nt][1] + inj1 + acc[mi][nt][r * 2 + 1];
                    const float s0 = (y0 >= THRESH) ? 1.0f : 0.0f;
                    const float s1 = (y1 >= THRESH) ? 1.0f : 0.0f;
                    V[mi][r][nt][0] = (y0 >= THRESH) ? 0.0f : y0;
                    V[mi][r][nt][1] = (y1 >= THRESH) ? 0.0f : y1;
                    sreg[mi][r][nt][0] = s0;
                    sreg[mi][r][nt][1] = s1;
                    __nv_bfloat162 sb2;
                    sb2.x = __float2bfloat16(s0);
                    sb2.y = __float2bfloat16(s1);
                    *(__nv_bfloat162*)&Sw[vi] = sb2;
                }
            }
        }

        // publish bf16 spikes to peers, then fill the barrier window with the
        // fp32 spike-record stores (consumed only by the final logits kernel)
        __syncthreads();
        const bool more = (t < T_STEPS - 1);
        if (more) bar_arrive(&s_gen);

        {
            float* outT = out + (size_t)t * BATCH * RES;
            #pragma unroll
            for (int mi = 0; mi < 2; mi++) {
                #pragma unroll
                for (int r = 0; r < 2; r++) {
                    const int b = m0 + wm * 32 + mi * 16 + r * 8 + lr;
                    #pragma unroll
                    for (int nt = 0; nt < 2; nt++) {
                        const int nl = wn * 16 + nt * 8 + lc * 2;
                        const size_t vi = (size_t)b * RES + n0 + nl;
                        float2 sp;
                        sp.x = sreg[mi][r][nt][0];
                        sp.y = sreg[mi][r][nt][1];
                        *(float2*)&outT[vi] = sp;
                    }
                }
            }
        }

        if (more) {
            bar_wait(&s_gen);
            // post-barrier: only A chunks 0..2 stand before the first MMA
            const char* gA2 = (const char*)g_S
                + (size_t)(t & 1) * BATCH * RES * 2 + (size_t)m0 * ROW_BYTES;
            #pragma unroll
            for (int p = 0; p < 3; p++) {
                load_tile256(sbA + p * A_STAGE, gA2 + (size_t)p * 128);
                CP_COMMIT();
            }
        }
    }
}

// ---------------------------------------------------------------------------
__global__ void __launch_bounds__(256)
logits_kernel(const float* __restrict__ spk,
              const float* __restrict__ Wout,
              float* __restrict__ logits)
{
    const int b = blockIdx.x;
    const int tid = threadIdx.x;
    float p0 = 0.0f, p1 = 0.0f;
    for (int r = tid; r < RES; r += 256) {
        float s = 0.0f;
        #pragma unroll
        for (int tt = 0; tt < 10; tt++)
            s += spk[((size_t)(T_STEPS - 10 + tt) * BATCH + b) * RES + r];
        s *= 0.1f;
        p0 = fmaf(s, Wout[r], p0);
        p1 = fmaf(s, Wout[RES + r], p1);
    }
    __shared__ float sh0[256];
    __shared__ float sh1[256];
    sh0[tid] = p0; sh1[tid] = p1;
    __syncthreads();
    for (int off = 128; off > 0; off >>= 1) {
        if (tid < off) { sh0[tid] += sh0[tid + off]; sh1[tid] += sh1[tid + off]; }
        __syncthreads();
    }
    if (tid == 0) {
        logits[b * OUTD + 0] = sh0[0];
        logits[b * OUTD + 1] = sh1[0];
    }
}

// ---------------------------------------------------------------------------
extern "C" void kernel_launch(void* const* d_in, const int* in_sizes, int n_in,
                              void* d_out, int out_size)
{
    const float* x    = (const float*)d_in[0];  // [200, 256, 3]
    const float* W    = (const float*)d_in[1];  // [2048, 2048]
    const float* Win  = (const float*)d_in[2];  // [2048, 3]
    const float* Wout = (const float*)d_in[3];  // [2, 2048]
    float* out = (float*)d_out;                 // spk [200*256*2048] | logits [256*2]

    cudaFuncSetAttribute(reservoir_kernel, cudaFuncAttributeMaxDynamicSharedMemorySize, SMEM_DYN);

    init_kernel<<<1, 32>>>();
    split_kernel<<<dim3(RES / 32, RES / 32), dim3(32, 8)>>>(W);

    dim3 grid(RES / BN, BATCH / BM);  // (32, 4) = 128 CTAs, all co-resident
    reservoir_kernel<<<grid, 256, SMEM_DYN>>>(x, Win, out);

    logits_kernel<<<BATCH, 256>>>(out, Wout, out + SPK_ELEMS);
}

// round 12
// speedup vs baseline: 1.8973x; 1.0737x over previous
#include <cuda_runtime.h>
#include <cuda_bf16.h>
#include <cstdint>

// ---------------- problem constants ----------------
#define T_STEPS 200
#define BATCH   256
#define RES     2048
#define OUTD    2
#define BETA    0.9f
#define THRESH  1.0f
#define SPK_ELEMS ((size_t)T_STEPS * BATCH * RES)
#define NSPLIT 3

// GEMM tiling: CTA 64(M) x 64(N), k-chunk 64, 256 threads (8 warps, 2x4),
// warp tile 32(M) x 16(N), mma.sync m16n8k16 bf16.
// Persistent kernel: one CTA/SM, PER-M-GROUP split-phase barriers (32 CTAs
// each; consumer (n,g) only depends on producers (*,g)), V in registers,
// fp32 spike stores deferred into the barrier window reusing acc registers.
// Split rings: A 4 x 8KB, B 6 x 24KB (B static across steps -> prefetched
// ACROSS the barrier with a continuous mod-6 slot counter).
#define BM 64
#define BN 64
#define BK 64
#define KCHUNKS (RES / BK)              // 32
#define ROW_BYTES 4096                  // 2048 bf16 per row
#define A_STAGE 8192
#define B_STAGE 24576
#define NB_STAGE 6
#define SMEM_DYN (4 * A_STAGE + NB_STAGE * B_STAGE)   // 180224
#define NGROUPBLK 32                    // CTAs per m-group barrier

// ---------------- device state ----------------
__device__ __nv_bfloat16 g_S[2 * BATCH * RES];                    // spike double buffer
__device__ __nv_bfloat16 g_W3[(size_t)NSPLIT * RES * RES];        // split W, [s][n][k]
__device__ unsigned g_bar_arrive[4];
__device__ unsigned g_bar_gen[4];

// ---------------- helpers ----------------
__device__ __forceinline__ uint32_t smem_u32(const void* p) {
    uint32_t a;
    asm("{ .reg .u64 t; cvta.to.shared.u64 t, %1; cvt.u32.u64 %0, t; }" : "=r"(a) : "l"(p));
    return a;
}

__device__ __forceinline__ void ldsm4(uint32_t* r, uint32_t addr) {
    asm volatile("ldmatrix.sync.aligned.m8n8.x4.shared.b16 {%0,%1,%2,%3}, [%4];"
                 : "=r"(r[0]), "=r"(r[1]), "=r"(r[2]), "=r"(r[3]) : "r"(addr));
}

__device__ __forceinline__ void mma16816(float* c, const uint32_t* a, uint32_t b0, uint32_t b1) {
    asm volatile("mma.sync.aligned.m16n8k16.row.col.f32.bf16.bf16.f32 "
                 "{%0,%1,%2,%3}, {%4,%5,%6,%7}, {%8,%9}, {%0,%1,%2,%3};"
                 : "+f"(c[0]), "+f"(c[1]), "+f"(c[2]), "+f"(c[3])
                 : "r"(a[0]), "r"(a[1]), "r"(a[2]), "r"(a[3]), "r"(b0), "r"(b1));
}

#define CP_COMMIT() asm volatile("cp.async.commit_group;" ::: "memory")
#define CP_WAIT2()  asm volatile("cp.async.wait_group 2;" ::: "memory")

// Split-phase per-group barrier (NGROUPBLK CTAs). All CTAs co-resident.
// bar_arrive must follow a __syncthreads covering the stores to publish.
__device__ __forceinline__ void bar_arrive(unsigned* arrive, unsigned* genp, unsigned* s_gen) {
    if (threadIdx.x == 0) {
        unsigned gen;
        asm volatile("ld.acquire.gpu.global.u32 %0, [%1];" : "=r"(gen) : "l"(genp));
        *s_gen = gen;
        unsigned prev;
        asm volatile("atom.add.release.gpu.global.u32 %0, [%1], %2;"
                     : "=r"(prev) : "l"(arrive), "r"(1u));
        if (prev == NGROUPBLK - 1) {
            asm volatile("st.relaxed.gpu.global.u32 [%0], %1;" :: "l"(arrive), "r"(0u));
            asm volatile("red.release.gpu.global.add.u32 [%0], %1;" :: "l"(genp), "r"(1u));
        }
    }
}
__device__ __forceinline__ void bar_wait(unsigned* genp, const unsigned* s_gen) {
    if (threadIdx.x == 0) {
        const unsigned gen = *s_gen;
        unsigned cur;
        do {
            asm volatile("ld.acquire.gpu.global.u32 %0, [%1];" : "=r"(cur) : "l"(genp));
        } while (cur == gen);
    }
    __syncthreads();
}

// 64x64 bf16 tile (8KB): rows of 128B = 8 x 16B chunks, chunk ^= row%8 swizzle.
// 256 threads, 2 x 16B cp.async each.
__device__ __forceinline__ void load_tile256(uint32_t sbase, const char* g) {
    const int tid = threadIdx.x;
    #pragma unroll
    for (int i = 0; i < 2; i++) {
        int c = tid + i * 256;
        int row = c >> 3, ch = c & 7;
        uint32_t dst = sbase + row * 128 + ((ch ^ (row & 7)) << 4);
        const char* src = g + (size_t)row * ROW_BYTES + ch * 16;
        asm volatile("cp.async.cg.shared.global [%0], [%1], 16;" :: "r"(dst), "l"(src));
    }
}

// load B for one chunk (3 split tiles) into one B stage
__device__ __forceinline__ void load_B(uint32_t stage, const char* gB, int chunk, size_t sstr) {
    #pragma unroll
    for (int s = 0; s < NSPLIT; s++)
        load_tile256(stage + s * A_STAGE, gB + (size_t)s * sstr + (size_t)chunk * 128);
}

// ---------------------------------------------------------------------------
__global__ void init_kernel() {
    const int i = threadIdx.x;
    if (i < 4) { g_bar_arrive[i] = 0u; g_bar_gen[i] = 0u; }
}

// split+transpose W: g_W3[s][n][k] = bf16 split s of W[k][n]
__global__ void split_kernel(const float* __restrict__ W) {
    __shared__ float sh[32][33];
    const int k0 = blockIdx.x * 32;
    const int n0 = blockIdx.y * 32;
    const int tx = threadIdx.x;
    const int ty = threadIdx.y;
    #pragma unroll
    for (int i = ty; i < 32; i += 8)
        sh[i][tx] = W[(size_t)(k0 + i) * RES + n0 + tx];
    __syncthreads();
    #pragma unroll
    for (int i = ty; i < 32; i += 8) {
        float w = sh[tx][i];  // = W[k0+tx][n0+i]
        __nv_bfloat16 b0 = __float2bfloat16(w);
        float r1 = w - __bfloat162float(b0);
        __nv_bfloat16 b1 = __float2bfloat16(r1);
        float r2 = r1 - __bfloat162float(b1);
        __nv_bfloat16 b2 = __float2bfloat16(r2);
        size_t o = (size_t)(n0 + i) * RES + k0 + tx;
        g_W3[o]                         = b0;
        g_W3[(size_t)RES * RES + o]     = b1;
        g_W3[(size_t)2 * RES * RES + o] = b2;
    }
}

// ---------------------------------------------------------------------------
// persistent reservoir kernel: all 200 timesteps, per-m-group barriers.
// ---------------------------------------------------------------------------
__global__ void __launch_bounds__(256, 1)
reservoir_kernel(const float* __restrict__ x,
                 const float* __restrict__ Win,
                 float* __restrict__ out)
{
    extern __shared__ __align__(128) char dsm[];
    __shared__ unsigned s_gen;

    const int tid  = threadIdx.x;
    const int lane = tid & 31;
    const int warp = tid >> 5;
    const int n0 = blockIdx.x * BN;
    const int m0 = blockIdx.y * BM;
    unsigned* bar_a = g_bar_arrive + blockIdx.y;
    unsigned* bar_g = g_bar_gen + blockIdx.y;
    const int wm = warp >> 2;        // 0..1 -> m offset *32
    const int wn = warp & 3;         // 0..3 -> n offset *16
    const int grp  = lane >> 3;      // ldmatrix address group
    const int lrow = lane & 7;
    const int lr = lane >> 2;        // mma frag row
    const int lc = lane & 3;         // mma frag col pair

    const uint32_t sbA = smem_u32(dsm);
    const uint32_t sbB = sbA + 4 * A_STAGE;
    const char* gB = (const char*)g_W3 + (size_t)n0 * ROW_BYTES;
    const size_t SSTR = (size_t)RES * RES * 2;   // split stride (bytes)

    // this thread's 4 epilogue n-columns: wn*16 + nt*8 + lc*2 + {0,1}
    float wv[4][3];
    #pragma unroll
    for (int nt = 0; nt < 2; nt++)
        #pragma unroll
        for (int q = 0; q < 2; q++) {
            const int nl = wn * 16 + nt * 8 + lc * 2 + q;
            wv[nt * 2 + q][0] = Win[(n0 + nl) * 3 + 0];
            wv[nt * 2 + q][1] = Win[(n0 + nl) * 3 + 1];
            wv[nt * 2 + q][2] = Win[(n0 + nl) * 3 + 2];
        }

    // ldmatrix per-thread row bases (constant across steps)
    const int rowA0 = wm * 32 + (grp & 1) * 8 + lrow;
    const int rowA1 = rowA0 + 16;
    const int rowB  = wn * 16 + (grp >> 1) * 8 + lrow;
    const uint32_t aOff0 = rowA0 * 128, aOff1 = rowA1 * 128, bOff = rowB * 128;
    const int a7_0 = rowA0 & 7, a7_1 = rowA1 & 7, b7 = rowB & 7;
    const int akh = grp >> 1, bkh = grp & 1;

    // membrane potential in registers: V[mi][r][nt][2]
    float V[2][2][2][2];
    #pragma unroll
    for (int a = 0; a < 2; a++)
        #pragma unroll
        for (int b = 0; b < 2; b++)
            #pragma unroll
            for (int c = 0; c < 2; c++)
                V[a][b][c][0] = V[a][b][c][1] = 0.0f;

    // preload B chunks 0..4 into B slots 0..4 (5 groups)
    #pragma unroll
    for (int p = 0; p < 5; p++) {
        load_B(sbB + p * B_STAGE, gB, p, SSTR);
        CP_COMMIT();
    }

    int bslot = 0;  // continuous B ring cursor (mod 6)

    #pragma unroll 1
    for (int t = 0; t < T_STEPS; t++) {
        float acc[2][2][4];
        #pragma unroll
        for (int a = 0; a < 2; a++)
            #pragma unroll
            for (int b = 0; b < 2; b++)
                #pragma unroll
                for (int c = 0; c < 4; c++) acc[a][b][c] = 0.0f;

        if (t > 0) {
            const char* gA = (const char*)g_S
                + (size_t)((t + 1) & 1) * BATCH * RES * 2 + (size_t)m0 * ROW_BYTES;

            #pragma unroll 1
            for (int c = 0; c < KCHUNKS; c++) {
                CP_WAIT2();
                __syncthreads();

                const uint32_t aT = sbA + (c & 3) * A_STAGE;
                const uint32_t bT = sbB + bslot * B_STAGE;

                #pragma unroll
                for (int kk = 0; kk < 4; kk++) {
                    uint32_t a0[4], a1[4];
                    ldsm4(a0, aT + aOff0 + ((((kk << 1) | akh) ^ a7_0) << 4));
                    ldsm4(a1, aT + aOff1 + ((((kk << 1) | akh) ^ a7_1) << 4));
                    #pragma unroll
                    for (int s = 0; s < NSPLIT; s++) {
                        uint32_t bb[4];
                        ldsm4(bb, bT + s * A_STAGE + bOff + ((((kk << 1) | bkh) ^ b7) << 4));
                        mma16816(acc[0][0], a0, bb[0], bb[1]);
                        mma16816(acc[0][1], a0, bb[2], bb[3]);
                        mma16816(acc[1][0], a1, bb[0], bb[1]);
                        mma16816(acc[1][1], a1, bb[2], bb[3]);
                    }
                }

                // prefetch: A distance 3 (same step only), B distance 5
                // (continuous — at c>=27 this preloads NEXT step's B chunks)
                const int an = c + 3;
                if (an < KCHUNKS)
                    load_tile256(sbA + (an & 3) * A_STAGE, gA + (size_t)an * 128);
                int bn = c + 5; if (bn >= KCHUNKS) bn -= KCHUNKS;
                int ps = bslot + 5; if (ps >= NB_STAGE) ps -= NB_STAGE;
                load_B(sbB + ps * B_STAGE, gB, bn, SSTR);
                CP_COMMIT();

                bslot = (bslot + 1 == NB_STAGE) ? 0 : bslot + 1;
            }
        }

        __syncthreads();

        // ---- fused LIF epilogue: update V, store bf16 spikes, park fp32
        //      spike values in the (now dead) acc registers ----
        const float* xt = x + (size_t)t * BATCH * 3;
        __nv_bfloat16* Sw = g_S + (size_t)(t & 1) * BATCH * RES;

        #pragma unroll
        for (int mi = 0; mi < 2; mi++) {
            #pragma unroll
            for (int r = 0; r < 2; r++) {
                const int b = m0 + wm * 32 + mi * 16 + r * 8 + lr;
                const float x0 = xt[b * 3 + 0];
                const float x1 = xt[b * 3 + 1];
                const float x2 = xt[b * 3 + 2];
                #pragma unroll
                for (int nt = 0; nt < 2; nt++) {
                    const int nl = wn * 16 + nt * 8 + lc * 2;
                    const size_t vi = (size_t)b * RES + n0 + nl;
                    const float inj0 = x0 * wv[nt * 2 + 0][0] + x1 * wv[nt * 2 + 0][1] + x2 * wv[nt * 2 + 0][2];
                    const float inj1 = x0 * wv[nt * 2 + 1][0] + x1 * wv[nt * 2 + 1][1] + x2 * wv[nt * 2 + 1][2];
                    const float y0 = BETA * V[mi][r][nt][0] + inj0 + acc[mi][nt][r * 2 + 0];
                    const float y1 = BETA * V[mi][r][nt][1] + inj1 + acc[mi][nt][r * 2 + 1];
                    const float s0 = (y0 >= THRESH) ? 1.0f : 0.0f;
                    const float s1 = (y1 >= THRESH) ? 1.0f : 0.0f;
                    V[mi][r][nt][0] = (y0 >= THRESH) ? 0.0f : y0;
                    V[mi][r][nt][1] = (y1 >= THRESH) ? 0.0f : y1;
                    acc[mi][nt][r * 2 + 0] = s0;   // park spike in dead acc reg
                    acc[mi][nt][r * 2 + 1] = s1;
                    __nv_bfloat162 sb2;
                    sb2.x = __float2bfloat16(s0);
                    sb2.y = __float2bfloat16(s1);
                    *(__nv_bfloat162*)&Sw[vi] = sb2;
                }
            }
        }

        // publish bf16 spikes to peers (release), then fill the barrier
        // window with fp32 spike-record stores (logits kernel input only)
        __syncthreads();
        const bool more = (t < T_STEPS - 1);
        if (more) bar_arrive(bar_a, bar_g, &s_gen);

        {
            float* outT = out + (size_t)t * BATCH * RES;
            #pragma unroll
            for (int mi = 0; mi < 2; mi++) {
                #pragma unroll
                for (int r = 0; r < 2; r++) {
                    const int b = m0 + wm * 32 + mi * 16 + r * 8 + lr;
                    #pragma unroll
                    for (int nt = 0; nt < 2; nt++) {
                        const int nl = wn * 16 + nt * 8 + lc * 2;
                        const size_t vi = (size_t)b * RES + n0 + nl;
                        float2 sp;
                        sp.x = acc[mi][nt][r * 2 + 0];
                        sp.y = acc[mi][nt][r * 2 + 1];
                        *(float2*)&outT[vi] = sp;
                    }
                }
            }
        }

        if (more) {
            bar_wait(bar_g, &s_gen);
            // post-barrier: only A chunks 0..2 stand before the first MMA
            const char* gA2 = (const char*)g_S
                + (size_t)(t & 1) * BATCH * RES * 2 + (size_t)m0 * ROW_BYTES;
            #pragma unroll
            for (int p = 0; p < 3; p++) {
                load_tile256(sbA + p * A_STAGE, gA2 + (size_t)p * 128);
                CP_COMMIT();
            }
        }
    }
}

// ---------------------------------------------------------------------------
__global__ void __launch_bounds__(256)
logits_kernel(const float* __restrict__ spk,
              const float* __restrict__ Wout,
              float* __restrict__ logits)
{
    const int b = blockIdx.x;
    const int tid = threadIdx.x;
    float p0 = 0.0f, p1 = 0.0f;
    for (int r = tid; r < RES; r += 256) {
        float s = 0.0f;
        #pragma unroll
        for (int tt = 0; tt < 10; tt++)
            s += spk[((size_t)(T_STEPS - 10 + tt) * BATCH + b) * RES + r];
        s *= 0.1f;
        p0 = fmaf(s, Wout[r], p0);
        p1 = fmaf(s, Wout[RES + r], p1);
    }
    __shared__ float sh0[256];
    __shared__ float sh1[256];
    sh0[tid] = p0; sh1[tid] = p1;
    __syncthreads();
    for (int off = 128; off > 0; off >>= 1) {
        if (tid < off) { sh0[tid] += sh0[tid + off]; sh1[tid] += sh1[tid + off]; }
        __syncthreads();
    }
    if (tid == 0) {
        logits[b * OUTD + 0] = sh0[0];
        logits[b * OUTD + 1] = sh1[0];
    }
}

// ---------------------------------------------------------------------------
extern "C" void kernel_launch(void* const* d_in, const int* in_sizes, int n_in,
                              void* d_out, int out_size)
{
    const float* x    = (const float*)d_in[0];  // [200, 256, 3]
    const float* W    = (const float*)d_in[1];  // [2048, 2048]
    const float* Win  = (const float*)d_in[2];  // [2048, 3]
    const float* Wout = (const float*)d_in[3];  // [2, 2048]
    float* out = (float*)d_out;                 // spk [200*256*2048] | logits [256*2]

    cudaFuncSetAttribute(reservoir_kernel, cudaFuncAttributeMaxDynamicSharedMemorySize, SMEM_DYN);

    init_kernel<<<1, 32>>>();
    split_kernel<<<dim3(RES / 32, RES / 32), dim3(32, 8)>>>(W);

    dim3 grid(RES / BN, BATCH / BM);  // (32, 4) = 128 CTAs, all co-resident
    reservoir_kernel<<<grid, 256, SMEM_DYN>>>(x, Win, out);

    logits_kernel<<<BATCH, 256>>>(out, Wout, out + SPK_ELEMS);
}